// round 1
// baseline (speedup 1.0000x reference)
#include <cuda_runtime.h>
#include <math.h>

// ---------------------------------------------------------------------------
// Problem constants
//   input  (8192, 2, 1024)  -> 16384 token rows of 1024
//   LayerNorm is JOINT over (S=2, E=1024) = 2048 elements per batch
//   head split: column c of q/k/v projection belongs to head (c % 16)
// ---------------------------------------------------------------------------
#define SCR_M 16777216ull   // 16384*1024 floats

// scratch layout (units of SCR_M floats):
// 0:xs  1:q  2:k  3:v  4:concat  5:out1  6:outs  7:hidden_s0  8:hidden_s1
__device__ __align__(256) float g_scratch[9ull * SCR_M];

// ---------------------------------------------------------------------------
// Joint LayerNorm over 2048 elements per batch. grid=8192, block=256.
// w,b are (2,1024) = 2048 contiguous floats, matching the flattened token pair.
// ---------------------------------------------------------------------------
__global__ void __launch_bounds__(256) ln_kernel(const float* __restrict__ x,
                                                 const float* __restrict__ w,
                                                 const float* __restrict__ bb,
                                                 float* __restrict__ y)
{
    int batch = blockIdx.x;
    int tid = threadIdx.x;
    const float4* xv = (const float4*)(x + (size_t)batch * 2048);
    float4 v0 = xv[tid];
    float4 v1 = xv[tid + 256];
    float s  = v0.x + v0.y + v0.z + v0.w + v1.x + v1.y + v1.z + v1.w;
    float ss = v0.x*v0.x + v0.y*v0.y + v0.z*v0.z + v0.w*v0.w
             + v1.x*v1.x + v1.y*v1.y + v1.z*v1.z + v1.w*v1.w;
#pragma unroll
    for (int o = 16; o > 0; o >>= 1) {
        s  += __shfl_xor_sync(0xffffffffu, s,  o);
        ss += __shfl_xor_sync(0xffffffffu, ss, o);
    }
    __shared__ float rs[8], rss[8];
    __shared__ float s_mean, s_rstd;
    if ((tid & 31) == 0) { rs[tid >> 5] = s; rss[tid >> 5] = ss; }
    __syncthreads();
    if (tid == 0) {
        float ts = 0.f, tss = 0.f;
#pragma unroll
        for (int i = 0; i < 8; i++) { ts += rs[i]; tss += rss[i]; }
        float m   = ts * (1.f / 2048.f);
        float var = tss * (1.f / 2048.f) - m * m;
        s_mean = m;
        s_rstd = rsqrtf(var + 1e-5f);
    }
    __syncthreads();
    float m = s_mean, r = s_rstd;
    const float4* wv = (const float4*)w;
    const float4* bv = (const float4*)bb;
    float4* yv = (float4*)(y + (size_t)batch * 2048);
    float4 w0 = wv[tid], w1 = wv[tid + 256];
    float4 b0 = bv[tid], b1 = bv[tid + 256];
    float4 o0, o1;
    o0.x = (v0.x - m) * r * w0.x + b0.x;
    o0.y = (v0.y - m) * r * w0.y + b0.y;
    o0.z = (v0.z - m) * r * w0.z + b0.z;
    o0.w = (v0.w - m) * r * w0.w + b0.w;
    o1.x = (v1.x - m) * r * w1.x + b1.x;
    o1.y = (v1.y - m) * r * w1.y + b1.y;
    o1.z = (v1.z - m) * r * w1.z + b1.z;
    o1.w = (v1.w - m) * r * w1.w + b1.w;
    yv[tid]       = o0;
    yv[tid + 256] = o1;
}

// ---------------------------------------------------------------------------
// Generic fp32 NT GEMM:  C[m,n] = epi( sum_k A[m,k] * B[n,k] )
//   A: row-major, row stride lda.   B: (N,K) row-major (stride K).
//   EPI: 0 = plain
//        1 = + res[m,n]                         (O-proj residual add)
//        2 = tanh(acc + bias[n])                (FFN layer 1)
//        3 = tanh(acc + bias[n]) + res[m,n]     (FFN layer 2 + residual)
// BM=BN=128, BK=16, 256 threads, 8x8 per thread. All dims divide tiles here.
// ---------------------------------------------------------------------------
#define BM 128
#define BN 128
#define BK 16
#define PAD 4

template <int EPI>
__global__ void __launch_bounds__(256) gemm_nt(
    const float* __restrict__ A, int lda,
    const float* __restrict__ Bw, int ldb,
    const float* __restrict__ bias,
    const float* __restrict__ res, int ldres,
    float* __restrict__ C, int ldc,
    int M, int N, int K)
{
    __shared__ __align__(16) float As[BK][BM + PAD];
    __shared__ __align__(16) float Bs[BK][BN + PAD];

    int bm = blockIdx.y * BM;
    int bn = blockIdx.x * BN;
    int tid = threadIdx.x;
    int tx = tid & 15;        // 0..15 -> n
    int ty = tid >> 4;        // 0..15 -> m

    float acc[8][8];
#pragma unroll
    for (int i = 0; i < 8; i++)
#pragma unroll
        for (int j = 0; j < 8; j++) acc[i][j] = 0.f;

    int lrow = tid >> 2;      // 0..63
    int lc4  = tid & 3;       // float4 index along k
    const float* Aptr = A  + (size_t)(bm + lrow) * lda + lc4 * 4;
    const float* Bptr = Bw + (size_t)(bn + lrow) * ldb + lc4 * 4;

    for (int k0 = 0; k0 < K; k0 += BK) {
        float4 a0 = *(const float4*)(Aptr + k0);
        float4 a1 = *(const float4*)(Aptr + (size_t)64 * lda + k0);
        float4 b0 = *(const float4*)(Bptr + k0);
        float4 b1 = *(const float4*)(Bptr + (size_t)64 * ldb + k0);

        As[lc4*4 + 0][lrow]      = a0.x;
        As[lc4*4 + 1][lrow]      = a0.y;
        As[lc4*4 + 2][lrow]      = a0.z;
        As[lc4*4 + 3][lrow]      = a0.w;
        As[lc4*4 + 0][lrow + 64] = a1.x;
        As[lc4*4 + 1][lrow + 64] = a1.y;
        As[lc4*4 + 2][lrow + 64] = a1.z;
        As[lc4*4 + 3][lrow + 64] = a1.w;

        Bs[lc4*4 + 0][lrow]      = b0.x;
        Bs[lc4*4 + 1][lrow]      = b0.y;
        Bs[lc4*4 + 2][lrow]      = b0.z;
        Bs[lc4*4 + 3][lrow]      = b0.w;
        Bs[lc4*4 + 0][lrow + 64] = b1.x;
        Bs[lc4*4 + 1][lrow + 64] = b1.y;
        Bs[lc4*4 + 2][lrow + 64] = b1.z;
        Bs[lc4*4 + 3][lrow + 64] = b1.w;

        __syncthreads();
#pragma unroll
        for (int kk = 0; kk < BK; kk++) {
            float4 av0 = *(const float4*)&As[kk][ty * 8];
            float4 av1 = *(const float4*)&As[kk][ty * 8 + 4];
            float4 bv0 = *(const float4*)&Bs[kk][tx * 8];
            float4 bv1 = *(const float4*)&Bs[kk][tx * 8 + 4];
            float am[8] = {av0.x, av0.y, av0.z, av0.w, av1.x, av1.y, av1.z, av1.w};
            float bm_[8] = {bv0.x, bv0.y, bv0.z, bv0.w, bv1.x, bv1.y, bv1.z, bv1.w};
#pragma unroll
            for (int i = 0; i < 8; i++)
#pragma unroll
                for (int j = 0; j < 8; j++)
                    acc[i][j] += am[i] * bm_[j];
        }
        __syncthreads();
    }

#pragma unroll
    for (int i = 0; i < 8; i++) {
        int row = bm + ty * 8 + i;
#pragma unroll
        for (int j = 0; j < 8; j++) {
            int col = bn + tx * 8 + j;
            float v = acc[i][j];
            if (EPI == 2 || EPI == 3) v = tanhf(v + bias[col]);
            if (EPI == 1 || EPI == 3) v += res[(size_t)row * ldres + col];
            C[(size_t)row * ldc + col] = v;
        }
    }
}

// ---------------------------------------------------------------------------
// Attention per batch. grid=8192, block=128.
// Column c belongs to head h = c%16; per head a 2x2 score/softmax; output
// concat[b,s,c] = p[h,s,0]*v[b,0,c] + p[h,s,1]*v[b,1,c]  (already in the
// (B,S,NH*H) "concat" layout the O-projection consumes).
// ---------------------------------------------------------------------------
__global__ void __launch_bounds__(128) attn_kernel(const float* __restrict__ q,
                                                   const float* __restrict__ k,
                                                   const float* __restrict__ v,
                                                   float* __restrict__ outc)
{
    int b = blockIdx.x;
    int tid = threadIdx.x;
    __shared__ float sq[2048], sk[2048], sv[2048];
    __shared__ float ssc[16][2][2];
    __shared__ float sp[16][2][2];

    const float4* qv = (const float4*)(q + (size_t)b * 2048);
    const float4* kv = (const float4*)(k + (size_t)b * 2048);
    const float4* vv = (const float4*)(v + (size_t)b * 2048);
#pragma unroll
    for (int i = tid; i < 512; i += 128) {
        ((float4*)sq)[i] = qv[i];
        ((float4*)sk)[i] = kv[i];
        ((float4*)sv)[i] = vv[i];
    }
    __syncthreads();

    if (tid < 64) {
        int h = tid >> 2, s = (tid >> 1) & 1, t = tid & 1;
        float acc = 0.f;
#pragma unroll 8
        for (int d = 0; d < 64; d++)
            acc += sq[s * 1024 + d * 16 + h] * sk[t * 1024 + d * 16 + h];
        ssc[h][s][t] = acc * 0.125f;   // 1/sqrt(64)
    }
    __syncthreads();

    if (tid < 32) {
        int h = tid >> 1, s = tid & 1;
        float a0 = ssc[h][s][0], a1 = ssc[h][s][1];
        float mx = fmaxf(a0, a1);
        float e0 = expf(a0 - mx), e1 = expf(a1 - mx);
        float inv = 1.f / (e0 + e1);
        sp[h][s][0] = e0 * inv;
        sp[h][s][1] = e1 * inv;
    }
    __syncthreads();

    float* ob = outc + (size_t)b * 2048;
#pragma unroll
    for (int i = tid; i < 2048; i += 128) {
        int s = i >> 10;
        int c = i & 1023;
        int h = c & 15;
        ob[i] = sp[h][s][0] * sv[c] + sp[h][s][1] * sv[1024 + c];
    }
}

// ---------------------------------------------------------------------------
// Orchestration. Inputs (metadata order):
//  0 input, 1 Wq, 2 Wk, 3 Wv, 4 Wo, 5 ln1_w, 6 ln1_b, 7 ln2_w, 8 ln2_b,
//  9 f1w1, 10 f1b1, 11 f1w2, 12 f1b2, 13 f2w1, 14 f2b1, 15 f2w2, 16 f2b2
// ---------------------------------------------------------------------------
extern "C" void kernel_launch(void* const* d_in, const int* in_sizes, int n_in,
                              void* d_out, int out_size)
{
    (void)in_sizes; (void)n_in; (void)out_size;
    const float* input = (const float*)d_in[0];
    const float* Wq    = (const float*)d_in[1];
    const float* Wk    = (const float*)d_in[2];
    const float* Wv    = (const float*)d_in[3];
    const float* Wo    = (const float*)d_in[4];
    const float* ln1w  = (const float*)d_in[5];
    const float* ln1b  = (const float*)d_in[6];
    const float* ln2w  = (const float*)d_in[7];
    const float* ln2b  = (const float*)d_in[8];
    const float* f1w1  = (const float*)d_in[9];
    const float* f1b1  = (const float*)d_in[10];
    const float* f1w2  = (const float*)d_in[11];
    const float* f1b2  = (const float*)d_in[12];
    const float* f2w1  = (const float*)d_in[13];
    const float* f2b1  = (const float*)d_in[14];
    const float* f2w2  = (const float*)d_in[15];
    const float* f2b2  = (const float*)d_in[16];
    float* out = (float*)d_out;

    float* S = nullptr;
    cudaGetSymbolAddress((void**)&S, g_scratch);
    float* xs     = S;
    float* q      = S + 1 * SCR_M;
    float* k      = S + 2 * SCR_M;
    float* v      = S + 3 * SCR_M;
    float* concat = S + 4 * SCR_M;
    float* out1   = S + 5 * SCR_M;
    float* outs   = S + 6 * SCR_M;
    float* h0     = S + 7 * SCR_M;   // 8192 x 2048
    float* h1     = S + 8 * SCR_M;   // 8192 x 2048

    // 1) LN1
    ln_kernel<<<8192, 256>>>(input, ln1w, ln1b, xs);

    // 2) Q,K,V projections: (16384x1024) @ W^T
    dim3 gQ(1024 / BN, 16384 / BM);
    gemm_nt<0><<<gQ, 256>>>(xs, 1024, Wq, 1024, nullptr, nullptr, 0, q, 1024, 16384, 1024, 1024);
    gemm_nt<0><<<gQ, 256>>>(xs, 1024, Wk, 1024, nullptr, nullptr, 0, k, 1024, 16384, 1024, 1024);
    gemm_nt<0><<<gQ, 256>>>(xs, 1024, Wv, 1024, nullptr, nullptr, 0, v, 1024, 16384, 1024, 1024);

    // 3) attention -> concat (B,S,NH*H)
    attn_kernel<<<8192, 128>>>(q, k, v, concat);

    // 4) O projection + residual: out1 = input + concat @ Wo^T
    gemm_nt<1><<<gQ, 256>>>(concat, 1024, Wo, 1024, nullptr, input, 1024, out1, 1024, 16384, 1024, 1024);

    // 5) LN2
    ln_kernel<<<8192, 256>>>(out1, ln2w, ln2b, outs);

    // 6) FFN layer 1 per sequence slot: hidden_s = tanh(outs[:,s,:] @ fsw1^T + fsb1)
    dim3 gF1(2048 / BN, 8192 / BM);
    gemm_nt<2><<<gF1, 256>>>(outs,        2048, f1w1, 1024, f1b1, nullptr, 0, h0, 2048, 8192, 2048, 1024);
    gemm_nt<2><<<gF1, 256>>>(outs + 1024, 2048, f2w1, 1024, f2b1, nullptr, 0, h1, 2048, 8192, 2048, 1024);

    // 7) FFN layer 2 + final residual: out[:,s,:] = tanh(h_s @ fsw2^T + fsb2) + out1[:,s,:]
    dim3 gF2(1024 / BN, 8192 / BM);
    gemm_nt<3><<<gF2, 256>>>(h0, 2048, f1w2, 2048, f1b2, out1,        2048, out,        2048, 8192, 1024, 2048);
    gemm_nt<3><<<gF2, 256>>>(h1, 2048, f2w2, 2048, f2b2, out1 + 1024, 2048, out + 1024, 2048, 8192, 1024, 2048);
}

// round 4
// speedup vs baseline: 1.6439x; 1.6439x over previous
#include <cuda_runtime.h>
#include <cuda_bf16.h>
#include <math.h>
#include <stdint.h>

// ===========================================================================
// B=8192, S=2, E=1024 -> 16384 token rows. All GEMMs NT vs (out,in) weights.
// GEMM path: mma.sync m16n8k16 bf16 3-term split (hi/lo), fp32 accumulators.
// (tcgen05 is NOT available: harness compiles PTX at .target sm_103, no 'a')
// ===========================================================================

#define NTOK 16384ull

__device__ __align__(256) float g_q[NTOK * 1024];
__device__ __align__(256) float g_k[NTOK * 1024];
__device__ __align__(256) float g_v[NTOK * 1024];
__device__ __align__(256) float g_out1[NTOK * 1024];
__device__ __align__(256) __nv_bfloat16 g_xs_hi[NTOK * 1024];
__device__ __align__(256) __nv_bfloat16 g_xs_lo[NTOK * 1024];
__device__ __align__(256) __nv_bfloat16 g_cc_hi[NTOK * 1024];
__device__ __align__(256) __nv_bfloat16 g_cc_lo[NTOK * 1024];
__device__ __align__(256) __nv_bfloat16 g_os_hi[NTOK * 1024];
__device__ __align__(256) __nv_bfloat16 g_os_lo[NTOK * 1024];
__device__ __align__(256) __nv_bfloat16 g_h_hi[2ull * 8192 * 2048];
__device__ __align__(256) __nv_bfloat16 g_h_lo[2ull * 8192 * 2048];
__device__ __align__(256) __nv_bfloat16 g_w_hi[12ull * 1024 * 1024];
__device__ __align__(256) __nv_bfloat16 g_w_lo[12ull * 1024 * 1024];

// ---------------- helpers ---------------------------------------------------
__device__ __forceinline__ uint32_t smem_u32(const void* p) {
    return (uint32_t)__cvta_generic_to_shared(p);
}
__device__ __forceinline__ void cp16(uint32_t dst, const void* src) {
    asm volatile("cp.async.cg.shared.global [%0], [%1], 16;\n" :: "r"(dst), "l"(src));
}
__device__ __forceinline__ void cp_commit() {
    asm volatile("cp.async.commit_group;\n" ::: "memory");
}
__device__ __forceinline__ void cp_wait1() {
    asm volatile("cp.async.wait_group 1;\n" ::: "memory");
}
__device__ __forceinline__ void ldsm4(uint32_t (&r)[4], uint32_t addr) {
    asm volatile("ldmatrix.sync.aligned.m8n8.x4.shared.b16 {%0,%1,%2,%3}, [%4];"
                 : "=r"(r[0]), "=r"(r[1]), "=r"(r[2]), "=r"(r[3]) : "r"(addr));
}
__device__ __forceinline__ void mma_bf16(float (&d)[4], const uint32_t (&a)[4],
                                         uint32_t b0, uint32_t b1) {
    asm volatile(
        "mma.sync.aligned.m16n8k16.row.col.f32.bf16.bf16.f32 "
        "{%0,%1,%2,%3}, {%4,%5,%6,%7}, {%8,%9}, {%0,%1,%2,%3};"
        : "+f"(d[0]), "+f"(d[1]), "+f"(d[2]), "+f"(d[3])
        : "r"(a[0]), "r"(a[1]), "r"(a[2]), "r"(a[3]), "r"(b0), "r"(b1));
}

__device__ __forceinline__ void split_store2(__nv_bfloat16* hi, __nv_bfloat16* lo,
                                             size_t idx, float a0, float a1) {
    __nv_bfloat16 h0 = __float2bfloat16(a0), h1 = __float2bfloat16(a1);
    __nv_bfloat16 l0 = __float2bfloat16(a0 - __bfloat162float(h0));
    __nv_bfloat16 l1 = __float2bfloat16(a1 - __bfloat162float(h1));
    *(__nv_bfloat162*)(hi + idx) = __halves2bfloat162(h0, h1);
    *(__nv_bfloat162*)(lo + idx) = __halves2bfloat162(l0, l1);
}
__device__ __forceinline__ void split_store4(__nv_bfloat16* hi, __nv_bfloat16* lo,
                                             size_t idx, float a0, float a1, float a2, float a3) {
    split_store2(hi, lo, idx, a0, a1);
    split_store2(hi, lo, idx + 2, a2, a3);
}

// ---------------------------------------------------------------------------
// Weight split: fp32 -> bf16 hi/lo
// ---------------------------------------------------------------------------
__global__ void __launch_bounds__(256) wconv(const float* __restrict__ w,
                                             __nv_bfloat16* __restrict__ hi,
                                             __nv_bfloat16* __restrict__ lo, int n) {
    int i = (blockIdx.x * 256 + threadIdx.x) * 4;
    if (i < n) {
        float4 v = *(const float4*)(w + i);
        split_store4(hi, lo, i, v.x, v.y, v.z, v.w);
    }
}

// ---------------------------------------------------------------------------
// Joint LayerNorm over 2048 elems per batch -> bf16 hi/lo
// ---------------------------------------------------------------------------
__global__ void __launch_bounds__(256) ln_kernel(const float* __restrict__ x,
                                                 const float* __restrict__ w,
                                                 const float* __restrict__ bb,
                                                 __nv_bfloat16* __restrict__ yhi,
                                                 __nv_bfloat16* __restrict__ ylo) {
    int batch = blockIdx.x;
    int tid = threadIdx.x;
    const float4* xv = (const float4*)(x + (size_t)batch * 2048);
    float4 v0 = xv[tid];
    float4 v1 = xv[tid + 256];
    float s  = v0.x + v0.y + v0.z + v0.w + v1.x + v1.y + v1.z + v1.w;
    float ss = v0.x*v0.x + v0.y*v0.y + v0.z*v0.z + v0.w*v0.w
             + v1.x*v1.x + v1.y*v1.y + v1.z*v1.z + v1.w*v1.w;
#pragma unroll
    for (int o = 16; o > 0; o >>= 1) {
        s  += __shfl_xor_sync(0xffffffffu, s,  o);
        ss += __shfl_xor_sync(0xffffffffu, ss, o);
    }
    __shared__ float rs[8], rss[8];
    __shared__ float s_mean, s_rstd;
    if ((tid & 31) == 0) { rs[tid >> 5] = s; rss[tid >> 5] = ss; }
    __syncthreads();
    if (tid == 0) {
        float ts = 0.f, tss = 0.f;
#pragma unroll
        for (int i = 0; i < 8; i++) { ts += rs[i]; tss += rss[i]; }
        float m   = ts * (1.f / 2048.f);
        float var = tss * (1.f / 2048.f) - m * m;
        s_mean = m;
        s_rstd = rsqrtf(var + 1e-5f);
    }
    __syncthreads();
    float m = s_mean, r = s_rstd;
    const float4* wv = (const float4*)w;
    const float4* bv = (const float4*)bb;
    float4 w0 = wv[tid], w1 = wv[tid + 256];
    float4 b0 = bv[tid], b1 = bv[tid + 256];
    size_t base = (size_t)batch * 2048 + tid * 4;
    split_store4(yhi, ylo, base,
                 (v0.x - m) * r * w0.x + b0.x, (v0.y - m) * r * w0.y + b0.y,
                 (v0.z - m) * r * w0.z + b0.z, (v0.w - m) * r * w0.w + b0.w);
    split_store4(yhi, ylo, base + 1024,
                 (v1.x - m) * r * w1.x + b1.x, (v1.y - m) * r * w1.y + b1.y,
                 (v1.z - m) * r * w1.z + b1.z, (v1.w - m) * r * w1.w + b1.w);
}

// ---------------------------------------------------------------------------
// Attention per batch (S=2; head h = col % 16) -> concat hi/lo bf16
// ---------------------------------------------------------------------------
__global__ void __launch_bounds__(128) attn_kernel(const float* __restrict__ q,
                                                   const float* __restrict__ k,
                                                   const float* __restrict__ v,
                                                   __nv_bfloat16* __restrict__ ohi,
                                                   __nv_bfloat16* __restrict__ olo) {
    int b = blockIdx.x;
    int tid = threadIdx.x;
    __shared__ float sq[2048], sk[2048], sv[2048];
    __shared__ float ssc[16][2][2];
    __shared__ float sp[16][2][2];

    const float4* qv = (const float4*)(q + (size_t)b * 2048);
    const float4* kv = (const float4*)(k + (size_t)b * 2048);
    const float4* vv = (const float4*)(v + (size_t)b * 2048);
#pragma unroll
    for (int i = tid; i < 512; i += 128) {
        ((float4*)sq)[i] = qv[i];
        ((float4*)sk)[i] = kv[i];
        ((float4*)sv)[i] = vv[i];
    }
    __syncthreads();

    if (tid < 64) {
        int h = tid >> 2, s = (tid >> 1) & 1, t = tid & 1;
        float acc = 0.f;
#pragma unroll 8
        for (int d = 0; d < 64; d++)
            acc += sq[s * 1024 + d * 16 + h] * sk[t * 1024 + d * 16 + h];
        ssc[h][s][t] = acc * 0.125f;
    }
    __syncthreads();

    if (tid < 32) {
        int h = tid >> 1, s = tid & 1;
        float a0 = ssc[h][s][0], a1 = ssc[h][s][1];
        float mx = fmaxf(a0, a1);
        float e0 = expf(a0 - mx), e1 = expf(a1 - mx);
        float inv = 1.f / (e0 + e1);
        sp[h][s][0] = e0 * inv;
        sp[h][s][1] = e1 * inv;
    }
    __syncthreads();

    size_t ob = (size_t)b * 2048;
#pragma unroll
    for (int i = tid; i < 2048; i += 128) {
        int s = i >> 10;
        int c = i & 1023;
        int h = c & 15;
        float val = sp[h][s][0] * sv[c] + sp[h][s][1] * sv[1024 + c];
        __nv_bfloat16 hv = __float2bfloat16(val);
        ohi[ob + i] = hv;
        olo[ob + i] = __float2bfloat16(val - __bfloat162float(hv));
    }
}

// ---------------------------------------------------------------------------
// mma.sync split-bf16 GEMM:  C = epi( A @ B^T ),  A:(M,K) hi/lo, B:(N,K) hi/lo.
// Tile 128x128x32, 8 warps (2M x 4N, each 64x32), double-buffered cp.async.
// smem rows are 64B (32 bf16); XOR swizzle chunk^=((row>>1)&3) for
// conflict-free ldmatrix AND conflict-free cp.async stores.
// EPI: 0 plain fp32; 1 +res; 2 tanh(+bias)->bf16 hi/lo; 3 tanh(+bias)+res
// ---------------------------------------------------------------------------
#define AHI_OFF 0
#define ALO_OFF 8192
#define BHI_OFF 16384
#define BLO_OFF 24576
#define STAGE_BYTES 32768
#define GEMM_SMEM (2 * STAGE_BYTES)

template <int EPI>
__global__ void __launch_bounds__(256) gemm_mma(
    const __nv_bfloat16* __restrict__ Ahi, const __nv_bfloat16* __restrict__ Alo, int lda,
    const __nv_bfloat16* __restrict__ Bhi, const __nv_bfloat16* __restrict__ Blo, int ldb,
    const float* __restrict__ bias,
    const float* __restrict__ res, int ldres,
    float* __restrict__ C, int ldc,
    __nv_bfloat16* __restrict__ Chi, __nv_bfloat16* __restrict__ Clo,
    int K)
{
    extern __shared__ __align__(128) char smem[];
    const uint32_t sb = smem_u32(smem);
    const int tid = threadIdx.x;
    const int wid = tid >> 5, lane = tid & 31;
    const int bm = blockIdx.y * 128, bn = blockIdx.x * 128;
    const int wm = wid & 1, wn = wid >> 1;
    const int nch = K / 32;

    float acc[4][4][4];
#pragma unroll
    for (int i = 0; i < 4; i++)
#pragma unroll
        for (int j = 0; j < 4; j++)
#pragma unroll
            for (int r = 0; r < 4; r++) acc[i][j][r] = 0.f;

    // ldmatrix per-lane geometry
    const int r16 = (lane & 7) + (((lane >> 3) & 1) << 3);  // row within 16
    const int cko = lane >> 4;                              // k-chunk add (0/1)
    uint32_t arow[4]; int axr[4];
#pragma unroll
    for (int tm = 0; tm < 4; tm++) {
        int row = wm * 64 + tm * 16 + r16;
        arow[tm] = row * 64;
        axr[tm] = (row >> 1) & 3;
    }
    uint32_t brow[2]; int bxr[2];
#pragma unroll
    for (int g = 0; g < 2; g++) {
        int row = wn * 32 + g * 16 + r16;
        brow[g] = row * 64;
        bxr[g] = (row >> 1) & 3;
    }

    auto load_stage = [&](int stage, int c) {
        if (c < nch) {
            const int k0 = c * 32;
            const uint32_t s0 = sb + stage * STAGE_BYTES;
#pragma unroll
            for (int j = 0; j < 2; j++) {
                int idx = tid + j * 256;
                int row = idx >> 2, cc = idx & 3;
                uint32_t soff = row * 64 + ((cc ^ ((row >> 1) & 3)) << 4);
                cp16(s0 + AHI_OFF + soff, Ahi + (size_t)(bm + row) * lda + k0 + cc * 8);
                cp16(s0 + ALO_OFF + soff, Alo + (size_t)(bm + row) * lda + k0 + cc * 8);
                cp16(s0 + BHI_OFF + soff, Bhi + (size_t)(bn + row) * ldb + k0 + cc * 8);
                cp16(s0 + BLO_OFF + soff, Blo + (size_t)(bn + row) * ldb + k0 + cc * 8);
            }
        }
        cp_commit();
    };

    load_stage(0, 0);
    load_stage(1, 1);

    for (int c = 0; c < nch; c++) {
        cp_wait1();
        __syncthreads();
        const uint32_t s0 = sb + (c & 1) * STAGE_BYTES;
#pragma unroll
        for (int kk = 0; kk < 2; kk++) {
            const int cb = kk * 2;
            uint32_t ah[4][4], al[4][4], bh[2][4], bl[2][4];
#pragma unroll
            for (int tm = 0; tm < 4; tm++) {
                uint32_t off = arow[tm] + (((cb | cko) ^ axr[tm]) << 4);
                ldsm4(ah[tm], s0 + AHI_OFF + off);
                ldsm4(al[tm], s0 + ALO_OFF + off);
            }
#pragma unroll
            for (int g = 0; g < 2; g++) {
                uint32_t off = brow[g] + (((cb | cko) ^ bxr[g]) << 4);
                ldsm4(bh[g], s0 + BHI_OFF + off);
                ldsm4(bl[g], s0 + BLO_OFF + off);
            }
#pragma unroll
            for (int tm = 0; tm < 4; tm++)
#pragma unroll
                for (int tn = 0; tn < 4; tn++) {
                    const int g = tn >> 1, h = tn & 1;
                    mma_bf16(acc[tm][tn], ah[tm], bh[g][h], bh[g][h + 2]);
                    mma_bf16(acc[tm][tn], ah[tm], bl[g][h], bl[g][h + 2]);
                    mma_bf16(acc[tm][tn], al[tm], bh[g][h], bh[g][h + 2]);
                }
        }
        __syncthreads();
        load_stage(c & 1, c + 2);
    }

    // Epilogue: acc[tm][tn]: rows bm+wm*64+tm*16+lane/4 (+8), cols bn+wn*32+tn*8+(lane%4)*2
#pragma unroll
    for (int tm = 0; tm < 4; tm++) {
#pragma unroll
        for (int tn = 0; tn < 4; tn++) {
            const int row0 = bm + wm * 64 + tm * 16 + (lane >> 2);
            const int col  = bn + wn * 32 + tn * 8 + (lane & 3) * 2;
#pragma unroll
            for (int hrow = 0; hrow < 2; hrow++) {
                const int row = row0 + hrow * 8;
                float d0 = acc[tm][tn][hrow * 2];
                float d1 = acc[tm][tn][hrow * 2 + 1];
                if (EPI == 0) {
                    *(float2*)(C + (size_t)row * ldc + col) = make_float2(d0, d1);
                } else if (EPI == 1) {
                    float2 rv = *(const float2*)(res + (size_t)row * ldres + col);
                    *(float2*)(C + (size_t)row * ldc + col) =
                        make_float2(d0 + rv.x, d1 + rv.y);
                } else if (EPI == 2) {
                    float2 bv = *(const float2*)(bias + col);
                    split_store2(Chi, Clo, (size_t)row * ldc + col,
                                 tanhf(d0 + bv.x), tanhf(d1 + bv.y));
                } else {
                    float2 bv = *(const float2*)(bias + col);
                    float2 rv = *(const float2*)(res + (size_t)row * ldres + col);
                    *(float2*)(C + (size_t)row * ldc + col) =
                        make_float2(tanhf(d0 + bv.x) + rv.x, tanhf(d1 + bv.y) + rv.y);
                }
            }
        }
    }
}

// ---------------------------------------------------------------------------
// Orchestration
// ---------------------------------------------------------------------------
extern "C" void kernel_launch(void* const* d_in, const int* in_sizes, int n_in,
                              void* d_out, int out_size) {
    (void)in_sizes; (void)n_in; (void)out_size;
    const float* input = (const float*)d_in[0];
    const float* Wq = (const float*)d_in[1];
    const float* Wk = (const float*)d_in[2];
    const float* Wv = (const float*)d_in[3];
    const float* Wo = (const float*)d_in[4];
    const float* ln1w = (const float*)d_in[5];
    const float* ln1b = (const float*)d_in[6];
    const float* ln2w = (const float*)d_in[7];
    const float* ln2b = (const float*)d_in[8];
    const float* f1w1 = (const float*)d_in[9];
    const float* f1b1 = (const float*)d_in[10];
    const float* f1w2 = (const float*)d_in[11];
    const float* f1b2 = (const float*)d_in[12];
    const float* f2w1 = (const float*)d_in[13];
    const float* f2b1 = (const float*)d_in[14];
    const float* f2w2 = (const float*)d_in[15];
    const float* f2b2 = (const float*)d_in[16];
    float* out = (float*)d_out;

    float *q, *k, *v, *out1;
    __nv_bfloat16 *xs_hi, *xs_lo, *cc_hi, *cc_lo, *os_hi, *os_lo, *h_hi, *h_lo, *w_hi, *w_lo;
    cudaGetSymbolAddress((void**)&q, g_q);
    cudaGetSymbolAddress((void**)&k, g_k);
    cudaGetSymbolAddress((void**)&v, g_v);
    cudaGetSymbolAddress((void**)&out1, g_out1);
    cudaGetSymbolAddress((void**)&xs_hi, g_xs_hi);
    cudaGetSymbolAddress((void**)&xs_lo, g_xs_lo);
    cudaGetSymbolAddress((void**)&cc_hi, g_cc_hi);
    cudaGetSymbolAddress((void**)&cc_lo, g_cc_lo);
    cudaGetSymbolAddress((void**)&os_hi, g_os_hi);
    cudaGetSymbolAddress((void**)&os_lo, g_os_lo);
    cudaGetSymbolAddress((void**)&h_hi, g_h_hi);
    cudaGetSymbolAddress((void**)&h_lo, g_h_lo);
    cudaGetSymbolAddress((void**)&w_hi, g_w_hi);
    cudaGetSymbolAddress((void**)&w_lo, g_w_lo);

    const size_t M1 = 1024ull * 1024;
    __nv_bfloat16 *wq_h = w_hi + 0*M1,  *wq_l = w_lo + 0*M1;
    __nv_bfloat16 *wk_h = w_hi + 1*M1,  *wk_l = w_lo + 1*M1;
    __nv_bfloat16 *wv_h = w_hi + 2*M1,  *wv_l = w_lo + 2*M1;
    __nv_bfloat16 *wo_h = w_hi + 3*M1,  *wo_l = w_lo + 3*M1;
    __nv_bfloat16 *f1w1_h = w_hi + 4*M1, *f1w1_l = w_lo + 4*M1;
    __nv_bfloat16 *f2w1_h = w_hi + 6*M1, *f2w1_l = w_lo + 6*M1;
    __nv_bfloat16 *f1w2_h = w_hi + 8*M1, *f1w2_l = w_lo + 8*M1;
    __nv_bfloat16 *f2w2_h = w_hi + 10*M1, *f2w2_l = w_lo + 10*M1;
    __nv_bfloat16 *h0_hi = h_hi, *h0_lo = h_lo;
    __nv_bfloat16 *h1_hi = h_hi + 8192ull * 2048, *h1_lo = h_lo + 8192ull * 2048;

    cudaFuncSetAttribute(gemm_mma<0>, cudaFuncAttributeMaxDynamicSharedMemorySize, GEMM_SMEM);
    cudaFuncSetAttribute(gemm_mma<1>, cudaFuncAttributeMaxDynamicSharedMemorySize, GEMM_SMEM);
    cudaFuncSetAttribute(gemm_mma<2>, cudaFuncAttributeMaxDynamicSharedMemorySize, GEMM_SMEM);
    cudaFuncSetAttribute(gemm_mma<3>, cudaFuncAttributeMaxDynamicSharedMemorySize, GEMM_SMEM);

    // weight splits
    wconv<<<1024, 256>>>(Wq, wq_h, wq_l, 1 << 20);
    wconv<<<1024, 256>>>(Wk, wk_h, wk_l, 1 << 20);
    wconv<<<1024, 256>>>(Wv, wv_h, wv_l, 1 << 20);
    wconv<<<1024, 256>>>(Wo, wo_h, wo_l, 1 << 20);
    wconv<<<2048, 256>>>(f1w1, f1w1_h, f1w1_l, 1 << 21);
    wconv<<<2048, 256>>>(f2w1, f2w1_h, f2w1_l, 1 << 21);
    wconv<<<2048, 256>>>(f1w2, f1w2_h, f1w2_l, 1 << 21);
    wconv<<<2048, 256>>>(f2w2, f2w2_h, f2w2_l, 1 << 21);

    // LN1 -> xs hi/lo
    ln_kernel<<<8192, 256>>>(input, ln1w, ln1b, xs_hi, xs_lo);

    // QKV projections (M=16384, N=1024, K=1024)
    dim3 g1(8, 128);
    gemm_mma<0><<<g1, 256, GEMM_SMEM>>>(xs_hi, xs_lo, 1024, wq_h, wq_l, 1024,
                                        nullptr, nullptr, 0, q, 1024, nullptr, nullptr, 1024);
    gemm_mma<0><<<g1, 256, GEMM_SMEM>>>(xs_hi, xs_lo, 1024, wk_h, wk_l, 1024,
                                        nullptr, nullptr, 0, k, 1024, nullptr, nullptr, 1024);
    gemm_mma<0><<<g1, 256, GEMM_SMEM>>>(xs_hi, xs_lo, 1024, wv_h, wv_l, 1024,
                                        nullptr, nullptr, 0, v, 1024, nullptr, nullptr, 1024);

    // attention -> concat hi/lo
    attn_kernel<<<8192, 128>>>(q, k, v, cc_hi, cc_lo);

    // O projection + residual -> out1 (fp32)
    gemm_mma<1><<<g1, 256, GEMM_SMEM>>>(cc_hi, cc_lo, 1024, wo_h, wo_l, 1024,
                                        nullptr, input, 1024, out1, 1024, nullptr, nullptr, 1024);

    // LN2 -> outs hi/lo
    ln_kernel<<<8192, 256>>>(out1, ln2w, ln2b, os_hi, os_lo);

    // FFN layer 1 per slot (M=8192, N=2048, K=1024) -> h hi/lo with tanh+bias
    dim3 g2(16, 64);
    gemm_mma<2><<<g2, 256, GEMM_SMEM>>>(os_hi, os_lo, 2048, f1w1_h, f1w1_l, 1024,
                                        f1b1, nullptr, 0, nullptr, 2048, h0_hi, h0_lo, 1024);
    gemm_mma<2><<<g2, 256, GEMM_SMEM>>>(os_hi + 1024, os_lo + 1024, 2048, f2w1_h, f2w1_l, 1024,
                                        f2b1, nullptr, 0, nullptr, 2048, h1_hi, h1_lo, 1024);

    // FFN layer 2 + residual (M=8192, N=1024, K=2048) -> out
    dim3 g3(8, 64);
    gemm_mma<3><<<g3, 256, GEMM_SMEM>>>(h0_hi, h0_lo, 2048, f1w2_h, f1w2_l, 2048,
                                        f1b2, out1, 2048, out, 2048, nullptr, nullptr, 2048);
    gemm_mma<3><<<g3, 256, GEMM_SMEM>>>(h1_hi, h1_lo, 2048, f2w2_h, f2w2_l, 2048,
                                        f2b2, out1 + 1024, 2048, out + 1024, 2048, nullptr, nullptr, 2048);
}

// round 5
// speedup vs baseline: 2.5066x; 1.5248x over previous
#include <cuda_runtime.h>
#include <cuda_bf16.h>
#include <math.h>
#include <stdint.h>

// ===========================================================================
// B=8192, S=2, E=1024 -> 16384 token rows. All GEMMs NT vs (out,in) weights.
// GEMM: mma.sync m16n8k16 bf16 3-term split (hi/lo), fp32 accum.
// R5: K-chunk 64, 3-stage cp.async pipeline, 1 barrier/chunk, early issue.
// ===========================================================================

#define NTOK 16384ull

__device__ __align__(256) float g_q[NTOK * 1024];
__device__ __align__(256) float g_k[NTOK * 1024];
__device__ __align__(256) float g_v[NTOK * 1024];
__device__ __align__(256) float g_out1[NTOK * 1024];
__device__ __align__(256) __nv_bfloat16 g_xs_hi[NTOK * 1024];
__device__ __align__(256) __nv_bfloat16 g_xs_lo[NTOK * 1024];
__device__ __align__(256) __nv_bfloat16 g_cc_hi[NTOK * 1024];
__device__ __align__(256) __nv_bfloat16 g_cc_lo[NTOK * 1024];
__device__ __align__(256) __nv_bfloat16 g_os_hi[NTOK * 1024];
__device__ __align__(256) __nv_bfloat16 g_os_lo[NTOK * 1024];
__device__ __align__(256) __nv_bfloat16 g_h_hi[2ull * 8192 * 2048];
__device__ __align__(256) __nv_bfloat16 g_h_lo[2ull * 8192 * 2048];
__device__ __align__(256) __nv_bfloat16 g_w_hi[12ull * 1024 * 1024];
__device__ __align__(256) __nv_bfloat16 g_w_lo[12ull * 1024 * 1024];

// ---------------- helpers ---------------------------------------------------
__device__ __forceinline__ uint32_t smem_u32(const void* p) {
    return (uint32_t)__cvta_generic_to_shared(p);
}
__device__ __forceinline__ void cp16(uint32_t dst, const void* src) {
    asm volatile("cp.async.cg.shared.global [%0], [%1], 16;\n" :: "r"(dst), "l"(src));
}
__device__ __forceinline__ void cp_commit() {
    asm volatile("cp.async.commit_group;\n" ::: "memory");
}
__device__ __forceinline__ void cp_wait1() {
    asm volatile("cp.async.wait_group 1;\n" ::: "memory");
}
__device__ __forceinline__ void ldsm4(uint32_t (&r)[4], uint32_t addr) {
    asm volatile("ldmatrix.sync.aligned.m8n8.x4.shared.b16 {%0,%1,%2,%3}, [%4];"
                 : "=r"(r[0]), "=r"(r[1]), "=r"(r[2]), "=r"(r[3]) : "r"(addr));
}
__device__ __forceinline__ void mma_bf16(float (&d)[4], const uint32_t (&a)[4],
                                         uint32_t b0, uint32_t b1) {
    asm volatile(
        "mma.sync.aligned.m16n8k16.row.col.f32.bf16.bf16.f32 "
        "{%0,%1,%2,%3}, {%4,%5,%6,%7}, {%8,%9}, {%0,%1,%2,%3};"
        : "+f"(d[0]), "+f"(d[1]), "+f"(d[2]), "+f"(d[3])
        : "r"(a[0]), "r"(a[1]), "r"(a[2]), "r"(a[3]), "r"(b0), "r"(b1));
}

__device__ __forceinline__ void split_store2(__nv_bfloat16* hi, __nv_bfloat16* lo,
                                             size_t idx, float a0, float a1) {
    __nv_bfloat16 h0 = __float2bfloat16(a0), h1 = __float2bfloat16(a1);
    __nv_bfloat16 l0 = __float2bfloat16(a0 - __bfloat162float(h0));
    __nv_bfloat16 l1 = __float2bfloat16(a1 - __bfloat162float(h1));
    *(__nv_bfloat162*)(hi + idx) = __halves2bfloat162(h0, h1);
    *(__nv_bfloat162*)(lo + idx) = __halves2bfloat162(l0, l1);
}
__device__ __forceinline__ void split_store4(__nv_bfloat16* hi, __nv_bfloat16* lo,
                                             size_t idx, float a0, float a1, float a2, float a3) {
    split_store2(hi, lo, idx, a0, a1);
    split_store2(hi, lo, idx + 2, a2, a3);
}

// ---------------------------------------------------------------------------
// Weight split (all 8 weights in one launch): fp32 -> bf16 hi/lo
// seg 0..3: 1M elems, dst offset seg*M1.  seg 4..7: 2M elems, dst (4+2*(seg-4))*M1
// ---------------------------------------------------------------------------
struct WPtrs { const float* w[8]; };

__global__ void __launch_bounds__(256) wconv8(WPtrs wp,
                                              __nv_bfloat16* __restrict__ hi,
                                              __nv_bfloat16* __restrict__ lo) {
    const size_t M1 = 1024ull * 1024;
    int bid = blockIdx.x;
    int seg, lb;
    size_t dstoff;
    if (bid < 4096) {
        seg = bid >> 10;
        lb = bid & 1023;
        dstoff = (size_t)seg * M1;
    } else {
        seg = 4 + ((bid - 4096) >> 11);
        lb = (bid - 4096) & 2047;
        dstoff = (size_t)(4 + 2 * (seg - 4)) * M1;
    }
    size_t i = ((size_t)lb * 256 + threadIdx.x) * 4;
    float4 v = *(const float4*)(wp.w[seg] + i);
    split_store4(hi + dstoff, lo + dstoff, i, v.x, v.y, v.z, v.w);
}

// ---------------------------------------------------------------------------
// Joint LayerNorm over 2048 elems per batch -> bf16 hi/lo
// ---------------------------------------------------------------------------
__global__ void __launch_bounds__(256) ln_kernel(const float* __restrict__ x,
                                                 const float* __restrict__ w,
                                                 const float* __restrict__ bb,
                                                 __nv_bfloat16* __restrict__ yhi,
                                                 __nv_bfloat16* __restrict__ ylo) {
    int batch = blockIdx.x;
    int tid = threadIdx.x;
    const float4* xv = (const float4*)(x + (size_t)batch * 2048);
    float4 v0 = xv[tid];
    float4 v1 = xv[tid + 256];
    float s  = v0.x + v0.y + v0.z + v0.w + v1.x + v1.y + v1.z + v1.w;
    float ss = v0.x*v0.x + v0.y*v0.y + v0.z*v0.z + v0.w*v0.w
             + v1.x*v1.x + v1.y*v1.y + v1.z*v1.z + v1.w*v1.w;
#pragma unroll
    for (int o = 16; o > 0; o >>= 1) {
        s  += __shfl_xor_sync(0xffffffffu, s,  o);
        ss += __shfl_xor_sync(0xffffffffu, ss, o);
    }
    __shared__ float rs[8], rss[8];
    __shared__ float s_mean, s_rstd;
    if ((tid & 31) == 0) { rs[tid >> 5] = s; rss[tid >> 5] = ss; }
    __syncthreads();
    if (tid == 0) {
        float ts = 0.f, tss = 0.f;
#pragma unroll
        for (int i = 0; i < 8; i++) { ts += rs[i]; tss += rss[i]; }
        float m   = ts * (1.f / 2048.f);
        float var = tss * (1.f / 2048.f) - m * m;
        s_mean = m;
        s_rstd = rsqrtf(var + 1e-5f);
    }
    __syncthreads();
    float m = s_mean, r = s_rstd;
    const float4* wv = (const float4*)w;
    const float4* bv = (const float4*)bb;
    float4 w0 = wv[tid], w1 = wv[tid + 256];
    float4 b0 = bv[tid], b1 = bv[tid + 256];
    size_t base = (size_t)batch * 2048 + tid * 4;
    split_store4(yhi, ylo, base,
                 (v0.x - m) * r * w0.x + b0.x, (v0.y - m) * r * w0.y + b0.y,
                 (v0.z - m) * r * w0.z + b0.z, (v0.w - m) * r * w0.w + b0.w);
    split_store4(yhi, ylo, base + 1024,
                 (v1.x - m) * r * w1.x + b1.x, (v1.y - m) * r * w1.y + b1.y,
                 (v1.z - m) * r * w1.z + b1.z, (v1.w - m) * r * w1.w + b1.w);
}

// ---------------------------------------------------------------------------
// Attention per batch (S=2; head h = col % 16) -> concat hi/lo bf16
// ---------------------------------------------------------------------------
__global__ void __launch_bounds__(128) attn_kernel(const float* __restrict__ q,
                                                   const float* __restrict__ k,
                                                   const float* __restrict__ v,
                                                   __nv_bfloat16* __restrict__ ohi,
                                                   __nv_bfloat16* __restrict__ olo) {
    int b = blockIdx.x;
    int tid = threadIdx.x;
    __shared__ float sq[2048], sk[2048], sv[2048];
    __shared__ float ssc[16][2][2];
    __shared__ float sp[16][2][2];

    const float4* qv = (const float4*)(q + (size_t)b * 2048);
    const float4* kv = (const float4*)(k + (size_t)b * 2048);
    const float4* vv = (const float4*)(v + (size_t)b * 2048);
#pragma unroll
    for (int i = tid; i < 512; i += 128) {
        ((float4*)sq)[i] = qv[i];
        ((float4*)sk)[i] = kv[i];
        ((float4*)sv)[i] = vv[i];
    }
    __syncthreads();

    if (tid < 64) {
        int h = tid >> 2, s = (tid >> 1) & 1, t = tid & 1;
        float acc = 0.f;
#pragma unroll 8
        for (int d = 0; d < 64; d++)
            acc += sq[s * 1024 + d * 16 + h] * sk[t * 1024 + d * 16 + h];
        ssc[h][s][t] = acc * 0.125f;
    }
    __syncthreads();

    if (tid < 32) {
        int h = tid >> 1, s = tid & 1;
        float a0 = ssc[h][s][0], a1 = ssc[h][s][1];
        float mx = fmaxf(a0, a1);
        float e0 = expf(a0 - mx), e1 = expf(a1 - mx);
        float inv = 1.f / (e0 + e1);
        sp[h][s][0] = e0 * inv;
        sp[h][s][1] = e1 * inv;
    }
    __syncthreads();

    size_t ob = (size_t)b * 2048;
#pragma unroll
    for (int i = tid; i < 2048; i += 128) {
        int s = i >> 10;
        int c = i & 1023;
        int h = c & 15;
        float val = sp[h][s][0] * sv[c] + sp[h][s][1] * sv[1024 + c];
        __nv_bfloat16 hv = __float2bfloat16(val);
        ohi[ob + i] = hv;
        olo[ob + i] = __float2bfloat16(val - __bfloat162float(hv));
    }
}

// ---------------------------------------------------------------------------
// mma.sync split-bf16 GEMM:  C = epi( A @ B^T ).
// Tile 128x128x64, 8 warps (2M x 4N, each 64x32), 3-stage cp.async pipeline,
// ONE __syncthreads per chunk, loads for c+2 issued before mma of c.
// smem rows 128B (64 bf16), SW128 swizzle: col16 ^ (row & 7).
// EPI: 0 plain fp32; 1 +res; 2 tanh(+bias)->bf16 hi/lo; 3 tanh(+bias)+res
// ---------------------------------------------------------------------------
#define AHI_OFF 0
#define ALO_OFF 16384
#define BHI_OFF 32768
#define BLO_OFF 49152
#define STAGE_BYTES 65536
#define NSTAGE 3
#define GEMM_SMEM (NSTAGE * STAGE_BYTES)

template <int EPI>
__global__ void __launch_bounds__(256, 1) gemm_mma(
    const __nv_bfloat16* __restrict__ Ahi, const __nv_bfloat16* __restrict__ Alo, int lda,
    const __nv_bfloat16* __restrict__ Bhi, const __nv_bfloat16* __restrict__ Blo, int ldb,
    const float* __restrict__ bias,
    const float* __restrict__ res, int ldres,
    float* __restrict__ C, int ldc,
    __nv_bfloat16* __restrict__ Chi, __nv_bfloat16* __restrict__ Clo,
    int K)
{
    extern __shared__ __align__(128) char smem[];
    const uint32_t sb = smem_u32(smem);
    const int tid = threadIdx.x;
    const int wid = tid >> 5, lane = tid & 31;
    const int bm = blockIdx.y * 128, bn = blockIdx.x * 128;
    const int wm = wid & 1, wn = wid >> 1;
    const int nch = K >> 6;

    float acc[4][4][4];
#pragma unroll
    for (int i = 0; i < 4; i++)
#pragma unroll
        for (int j = 0; j < 4; j++)
#pragma unroll
            for (int r = 0; r < 4; r++) acc[i][j][r] = 0.f;

    // ---- per-thread load geometry: 4 passes x 4 matrices, 16B each --------
    // pass j: idx = tid + j*256; row = idx>>3 (0..127), col16 = idx&7
    uint32_t soff[4];     // swizzled smem offset within a matrix
    uint32_t aoff[4];     // byte offset into A hi/lo (chunk 0)
    uint32_t boff[4];     // byte offset into B hi/lo (chunk 0)
#pragma unroll
    for (int j = 0; j < 4; j++) {
        int idx = tid + j * 256;
        int row = idx >> 3, c16 = idx & 7;
        soff[j] = row * 128 + ((c16 ^ (row & 7)) << 4);
        aoff[j] = (uint32_t)(((bm + row) * lda + c16 * 8) * 2);
        boff[j] = (uint32_t)(((bn + row) * ldb + c16 * 8) * 2);
    }
    const char* Ah = (const char*)Ahi;
    const char* Al = (const char*)Alo;
    const char* Bh = (const char*)Bhi;
    const char* Bl = (const char*)Blo;

    auto load_stage = [&](int stage, int c) {
        if (c < nch) {
            const uint32_t s0 = sb + stage * STAGE_BYTES;
            const uint32_t kadd = (uint32_t)c << 7;   // c*128 bytes
#pragma unroll
            for (int j = 0; j < 4; j++) {
                cp16(s0 + AHI_OFF + soff[j], Ah + aoff[j] + kadd);
                cp16(s0 + ALO_OFF + soff[j], Al + aoff[j] + kadd);
                cp16(s0 + BHI_OFF + soff[j], Bh + boff[j] + kadd);
                cp16(s0 + BLO_OFF + soff[j], Bl + boff[j] + kadd);
            }
        }
        cp_commit();
    };

    // ---- ldmatrix per-lane geometry ---------------------------------------
    const int r16 = (lane & 7) + (((lane >> 3) & 1) << 3);
    const int cko = lane >> 4;                       // 16B unit within 32B k16
    uint32_t arow[4]; int axr[4];
#pragma unroll
    for (int tm = 0; tm < 4; tm++) {
        int row = wm * 64 + tm * 16 + r16;
        arow[tm] = row * 128;
        axr[tm] = row & 7;
    }
    uint32_t brow[2]; int bxr[2];
#pragma unroll
    for (int g = 0; g < 2; g++) {
        int row = wn * 32 + g * 16 + r16;
        brow[g] = row * 128;
        bxr[g] = row & 7;
    }

    load_stage(0, 0);
    load_stage(1, 1);

    int stage = 0;
    for (int c = 0; c < nch; c++) {
        cp_wait1();           // chunk c resident
        __syncthreads();      // all smem visible; all warps done with c-1
        // issue loads for c+2 into the stage chunk c-1 used (safe: barrier above)
        int nstage = stage + 2;
        if (nstage >= NSTAGE) nstage -= NSTAGE;
        load_stage(nstage, c + 2);

        const uint32_t s0 = sb + stage * STAGE_BYTES;
#pragma unroll
        for (int kk = 0; kk < 4; kk++) {
            const int j16 = (kk << 1) | cko;
            uint32_t ah[4][4], al[4][4], bh[2][4], bl[2][4];
#pragma unroll
            for (int tm = 0; tm < 4; tm++) {
                uint32_t off = arow[tm] + ((j16 ^ axr[tm]) << 4);
                ldsm4(ah[tm], s0 + AHI_OFF + off);
                ldsm4(al[tm], s0 + ALO_OFF + off);
            }
#pragma unroll
            for (int g = 0; g < 2; g++) {
                uint32_t off = brow[g] + ((j16 ^ bxr[g]) << 4);
                ldsm4(bh[g], s0 + BHI_OFF + off);
                ldsm4(bl[g], s0 + BLO_OFF + off);
            }
#pragma unroll
            for (int tm = 0; tm < 4; tm++)
#pragma unroll
                for (int tn = 0; tn < 4; tn++) {
                    const int g = tn >> 1, h = tn & 1;
                    mma_bf16(acc[tm][tn], ah[tm], bh[g][h], bh[g][h + 2]);
                    mma_bf16(acc[tm][tn], ah[tm], bl[g][h], bl[g][h + 2]);
                    mma_bf16(acc[tm][tn], al[tm], bh[g][h], bh[g][h + 2]);
                }
        }
        if (++stage >= NSTAGE) stage -= NSTAGE;
    }

    // Epilogue
#pragma unroll
    for (int tm = 0; tm < 4; tm++) {
#pragma unroll
        for (int tn = 0; tn < 4; tn++) {
            const int row0 = bm + wm * 64 + tm * 16 + (lane >> 2);
            const int col  = bn + wn * 32 + tn * 8 + (lane & 3) * 2;
#pragma unroll
            for (int hrow = 0; hrow < 2; hrow++) {
                const int row = row0 + hrow * 8;
                float d0 = acc[tm][tn][hrow * 2];
                float d1 = acc[tm][tn][hrow * 2 + 1];
                if (EPI == 0) {
                    *(float2*)(C + (size_t)row * ldc + col) = make_float2(d0, d1);
                } else if (EPI == 1) {
                    float2 rv = *(const float2*)(res + (size_t)row * ldres + col);
                    *(float2*)(C + (size_t)row * ldc + col) =
                        make_float2(d0 + rv.x, d1 + rv.y);
                } else if (EPI == 2) {
                    float2 bv = *(const float2*)(bias + col);
                    split_store2(Chi, Clo, (size_t)row * ldc + col,
                                 tanhf(d0 + bv.x), tanhf(d1 + bv.y));
                } else {
                    float2 bv = *(const float2*)(bias + col);
                    float2 rv = *(const float2*)(res + (size_t)row * ldres + col);
                    *(float2*)(C + (size_t)row * ldc + col) =
                        make_float2(tanhf(d0 + bv.x) + rv.x, tanhf(d1 + bv.y) + rv.y);
                }
            }
        }
    }
}

// ---------------------------------------------------------------------------
// Orchestration
// ---------------------------------------------------------------------------
extern "C" void kernel_launch(void* const* d_in, const int* in_sizes, int n_in,
                              void* d_out, int out_size) {
    (void)in_sizes; (void)n_in; (void)out_size;
    const float* input = (const float*)d_in[0];
    const float* ln1w = (const float*)d_in[5];
    const float* ln1b = (const float*)d_in[6];
    const float* ln2w = (const float*)d_in[7];
    const float* ln2b = (const float*)d_in[8];
    const float* f1b1 = (const float*)d_in[10];
    const float* f1b2 = (const float*)d_in[12];
    const float* f2b1 = (const float*)d_in[14];
    const float* f2b2 = (const float*)d_in[16];
    float* out = (float*)d_out;

    float *q, *k, *v, *out1;
    __nv_bfloat16 *xs_hi, *xs_lo, *cc_hi, *cc_lo, *os_hi, *os_lo, *h_hi, *h_lo, *w_hi, *w_lo;
    cudaGetSymbolAddress((void**)&q, g_q);
    cudaGetSymbolAddress((void**)&k, g_k);
    cudaGetSymbolAddress((void**)&v, g_v);
    cudaGetSymbolAddress((void**)&out1, g_out1);
    cudaGetSymbolAddress((void**)&xs_hi, g_xs_hi);
    cudaGetSymbolAddress((void**)&xs_lo, g_xs_lo);
    cudaGetSymbolAddress((void**)&cc_hi, g_cc_hi);
    cudaGetSymbolAddress((void**)&cc_lo, g_cc_lo);
    cudaGetSymbolAddress((void**)&os_hi, g_os_hi);
    cudaGetSymbolAddress((void**)&os_lo, g_os_lo);
    cudaGetSymbolAddress((void**)&h_hi, g_h_hi);
    cudaGetSymbolAddress((void**)&h_lo, g_h_lo);
    cudaGetSymbolAddress((void**)&w_hi, g_w_hi);
    cudaGetSymbolAddress((void**)&w_lo, g_w_lo);

    const size_t M1 = 1024ull * 1024;
    __nv_bfloat16 *wq_h = w_hi + 0*M1,  *wq_l = w_lo + 0*M1;
    __nv_bfloat16 *wk_h = w_hi + 1*M1,  *wk_l = w_lo + 1*M1;
    __nv_bfloat16 *wv_h = w_hi + 2*M1,  *wv_l = w_lo + 2*M1;
    __nv_bfloat16 *wo_h = w_hi + 3*M1,  *wo_l = w_lo + 3*M1;
    __nv_bfloat16 *f1w1_h = w_hi + 4*M1, *f1w1_l = w_lo + 4*M1;
    __nv_bfloat16 *f2w1_h = w_hi + 6*M1, *f2w1_l = w_lo + 6*M1;
    __nv_bfloat16 *f1w2_h = w_hi + 8*M1, *f1w2_l = w_lo + 8*M1;
    __nv_bfloat16 *f2w2_h = w_hi + 10*M1, *f2w2_l = w_lo + 10*M1;
    __nv_bfloat16 *h0_hi = h_hi, *h0_lo = h_lo;
    __nv_bfloat16 *h1_hi = h_hi + 8192ull * 2048, *h1_lo = h_lo + 8192ull * 2048;

    cudaFuncSetAttribute(gemm_mma<0>, cudaFuncAttributeMaxDynamicSharedMemorySize, GEMM_SMEM);
    cudaFuncSetAttribute(gemm_mma<1>, cudaFuncAttributeMaxDynamicSharedMemorySize, GEMM_SMEM);
    cudaFuncSetAttribute(gemm_mma<2>, cudaFuncAttributeMaxDynamicSharedMemorySize, GEMM_SMEM);
    cudaFuncSetAttribute(gemm_mma<3>, cudaFuncAttributeMaxDynamicSharedMemorySize, GEMM_SMEM);

    // weight splits (ordering matches w_hi/w_lo layout above)
    WPtrs wp;
    wp.w[0] = (const float*)d_in[1];   // Wq
    wp.w[1] = (const float*)d_in[2];   // Wk
    wp.w[2] = (const float*)d_in[3];   // Wv
    wp.w[3] = (const float*)d_in[4];   // Wo
    wp.w[4] = (const float*)d_in[9];   // f1w1
    wp.w[5] = (const float*)d_in[13];  // f2w1
    wp.w[6] = (const float*)d_in[11];  // f1w2
    wp.w[7] = (const float*)d_in[15];  // f2w2
    wconv8<<<12288, 256>>>(wp, w_hi, w_lo);

    // LN1 -> xs hi/lo
    ln_kernel<<<8192, 256>>>(input, ln1w, ln1b, xs_hi, xs_lo);

    // QKV projections (M=16384, N=1024, K=1024)
    dim3 g1(8, 128);
    gemm_mma<0><<<g1, 256, GEMM_SMEM>>>(xs_hi, xs_lo, 1024, wq_h, wq_l, 1024,
                                        nullptr, nullptr, 0, q, 1024, nullptr, nullptr, 1024);
    gemm_mma<0><<<g1, 256, GEMM_SMEM>>>(xs_hi, xs_lo, 1024, wk_h, wk_l, 1024,
                                        nullptr, nullptr, 0, k, 1024, nullptr, nullptr, 1024);
    gemm_mma<0><<<g1, 256, GEMM_SMEM>>>(xs_hi, xs_lo, 1024, wv_h, wv_l, 1024,
                                        nullptr, nullptr, 0, v, 1024, nullptr, nullptr, 1024);

    // attention -> concat hi/lo
    attn_kernel<<<8192, 128>>>(q, k, v, cc_hi, cc_lo);

    // O projection + residual -> out1 (fp32)
    gemm_mma<1><<<g1, 256, GEMM_SMEM>>>(cc_hi, cc_lo, 1024, wo_h, wo_l, 1024,
                                        nullptr, input, 1024, out1, 1024, nullptr, nullptr, 1024);

    // LN2 -> outs hi/lo
    ln_kernel<<<8192, 256>>>(out1, ln2w, ln2b, os_hi, os_lo);

    // FFN layer 1 per slot (M=8192, N=2048, K=1024) -> h hi/lo with tanh+bias
    dim3 g2(16, 64);
    gemm_mma<2><<<g2, 256, GEMM_SMEM>>>(os_hi, os_lo, 2048, f1w1_h, f1w1_l, 1024,
                                        f1b1, nullptr, 0, nullptr, 2048, h0_hi, h0_lo, 1024);
    gemm_mma<2><<<g2, 256, GEMM_SMEM>>>(os_hi + 1024, os_lo + 1024, 2048, f2w1_h, f2w1_l, 1024,
                                        f2b1, nullptr, 0, nullptr, 2048, h1_hi, h1_lo, 1024);

    // FFN layer 2 + residual (M=8192, N=1024, K=2048) -> out
    dim3 g3(8, 64);
    gemm_mma<3><<<g3, 256, GEMM_SMEM>>>(h0_hi, h0_lo, 2048, f1w2_h, f1w2_l, 2048,
                                        f1b2, out1, 2048, out, 2048, nullptr, nullptr, 2048);
    gemm_mma<3><<<g3, 256, GEMM_SMEM>>>(h1_hi, h1_lo, 2048, f2w2_h, f2w2_l, 2048,
                                        f2b2, out1 + 1024, 2048, out + 1024, 2048, nullptr, nullptr, 2048);
}